// round 7
// baseline (speedup 1.0000x reference)
#include <cuda_runtime.h>
#include <cuda_bf16.h>
#include <cstdint>

#define Bb 2
#define Ll 32768
#define Cc 128
#define NTOK 512
#define HD 32

// ---- smem byte offsets ----
#define KH_OFF  0           // K hi: 512 rows x 64B (swizzled)     32768
#define KL_OFF  32768       // K lo                                32768
#define VTH_OFF 65536       // V^T hi: 32 d-rows x 1024B (swz)     32768
#define VTL_OFF 98304       // V^T lo                              32768
#define VF_OFF  131072      // V fp32 [512][36]                    73728
#define WS_OFF  204800      // weights [27][32] f32                 3456
#define BS_OFF  208256      // bias [32] f32                         128
#define SMEM_BYTES 208384
#define OS_OFF  0           // O fp32 [512][36] overlays K/VT after mainloop

static __device__ __forceinline__ float ex2f(float x){
    float y; asm("ex2.approx.ftz.f32 %0, %1;" : "=f"(y) : "f"(x)); return y;
}
static __device__ __forceinline__ uint32_t s2u(const void* p){
    uint32_t a;
    asm("{ .reg .u64 t; cvta.to.shared.u64 t, %1; cvt.u32.u64 %0, t; }" : "=r"(a) : "l"(p));
    return a;
}
// pack two f32 -> bf16x2 (a -> low half, b -> high half)
static __device__ __forceinline__ uint32_t pk2(float a, float b){
    uint32_t r; asm("cvt.rn.bf16x2.f32 %0, %1, %2;" : "=r"(r) : "f"(b), "f"(a)); return r;
}
// hi/lo split of a pair
static __device__ __forceinline__ void hilo2(float x, float y, uint32_t& h, uint32_t& l){
    h = pk2(x, y);
    float fx = __uint_as_float(h << 16);
    float fy = __uint_as_float(h & 0xffff0000u);
    l = pk2(x - fx, y - fy);
}
static __device__ __forceinline__ void ldm4(uint32_t* r, uint32_t a){
    asm volatile("ldmatrix.sync.aligned.m8n8.x4.shared.b16 {%0,%1,%2,%3}, [%4];"
        : "=r"(r[0]), "=r"(r[1]), "=r"(r[2]), "=r"(r[3]) : "r"(a));
}
static __device__ __forceinline__ void mma16816(float* d, const uint32_t* a, uint32_t b0, uint32_t b1){
    asm volatile("mma.sync.aligned.m16n8k16.row.col.f32.bf16.bf16.f32 "
        "{%0,%1,%2,%3},{%4,%5,%6,%7},{%8,%9},{%0,%1,%2,%3};"
        : "+f"(d[0]), "+f"(d[1]), "+f"(d[2]), "+f"(d[3])
        : "r"(a[0]), "r"(a[1]), "r"(a[2]), "r"(a[3]), "r"(b0), "r"(b1));
}
static __device__ __forceinline__ void sts_u16(uint32_t a, uint32_t v){
    asm volatile("st.shared.u16 [%0], %1;" :: "r"(a), "h"((unsigned short)v) : "memory");
}
static __device__ __forceinline__ void sts_v4(uint32_t a, uint32_t x, uint32_t y, uint32_t z, uint32_t w){
    asm volatile("st.shared.v4.b32 [%0], {%1,%2,%3,%4};" :: "r"(a), "r"(x), "r"(y), "r"(z), "r"(w) : "memory");
}
// K row addressing: 64B rows; 16B-chunk c rotated by (row>>1) so ldmatrix (8 rows, fixed c) is conflict-free
static __device__ __forceinline__ uint32_t kaddr(int n, int c){
    return (uint32_t)n*64u + ((((uint32_t)c + ((uint32_t)n >> 1)) & 3u) * 16u);
}
// V^T addressing: 1024B d-rows; low 3 bits of key-chunk XOR d
static __device__ __forceinline__ uint32_t vtaddr(int d, int kc){
    uint32_t sw = ((uint32_t)kc & ~7u) | (((uint32_t)(kc ^ d)) & 7u);
    return (uint32_t)d*1024u + sw*16u;
}

__global__ void __launch_bounds__(512, 1)
lepe_hmma(const float* __restrict__ qkv,
          const float* __restrict__ lw,
          const float* __restrict__ lb,
          float* __restrict__ out)
{
    extern __shared__ char sm[];
    const uint32_t smb = s2u(sm);
    const int tid = threadIdx.x;
    const int wid = tid >> 5, lane = tid & 31;

    const int bx = blockIdx.x;            // (window, head)
    const int win = bx >> 2, head = bx & 3;
    const int b  = win >> 6;
    const int tB = (win >> 4) & 3;
    const int wB = win & 15;
    const size_t batch_off = (size_t)b * Ll * Cc;
    const int chan  = head * HD;
    const int lbase = tB*8192 + wB*4;

    const float* qg = qkv + batch_off;
    const float* kg = qkv + (size_t)1*Bb*Ll*Cc + batch_off;
    const float* vg = qkv + (size_t)2*Bb*Ll*Cc + batch_off;

    // ---------- stage K (hi/lo), V^T (hi/lo), V fp32 ----------
    {
        const int q = tid & 3;            // 4 threads per row, 8 d-values each
        const int rbase = tid >> 2;       // 0..127
        for (int it = 0; it < 4; it++){
            const int j = it*128 + rbase;
            const int t = j >> 8, h = (j >> 2) & 63, ws = j & 3;
            const size_t l = (size_t)(lbase + t*4096 + h*64 + ws);
            const float4 k0 = *(const float4*)(kg + l*Cc + chan + q*8);
            const float4 k1 = *(const float4*)(kg + l*Cc + chan + q*8 + 4);
            uint32_t hh[4], ll[4];
            hilo2(k0.x, k0.y, hh[0], ll[0]);
            hilo2(k0.z, k0.w, hh[1], ll[1]);
            hilo2(k1.x, k1.y, hh[2], ll[2]);
            hilo2(k1.z, k1.w, hh[3], ll[3]);
            const uint32_t ka = kaddr(j, q);
            sts_v4(smb + KH_OFF + ka, hh[0], hh[1], hh[2], hh[3]);
            sts_v4(smb + KL_OFF + ka, ll[0], ll[1], ll[2], ll[3]);

            const float4 v0 = *(const float4*)(vg + l*Cc + chan + q*8);
            const float4 v1 = *(const float4*)(vg + l*Cc + chan + q*8 + 4);
            *(float4*)(sm + VF_OFF + j*144 + q*32)      = v0;
            *(float4*)(sm + VF_OFF + j*144 + q*32 + 16) = v1;
            hilo2(v0.x, v0.y, hh[0], ll[0]);
            hilo2(v0.z, v0.w, hh[1], ll[1]);
            hilo2(v1.x, v1.y, hh[2], ll[2]);
            hilo2(v1.z, v1.w, hh[3], ll[3]);
            const int kc = j >> 3;
            const uint32_t ko = (uint32_t)(j & 7) * 2u;
            #pragma unroll
            for (int e = 0; e < 8; e++){
                const int d = q*8 + e;
                const uint32_t hb  = (e & 1) ? (hh[e>>1] >> 16) : (hh[e>>1] & 0xffffu);
                const uint32_t lbv = (e & 1) ? (ll[e>>1] >> 16) : (ll[e>>1] & 0xffffu);
                const uint32_t va = vtaddr(d, kc) + ko;
                sts_u16(smb + VTH_OFF + va, hb);
                sts_u16(smb + VTL_OFF + va, lbv);
            }
        }
        for (int idx = tid; idx < 27*32; idx += 512){
            const int tap = idx >> 5, d = idx & 31;
            ((float*)(sm + WS_OFF))[tap*32 + d] = lw[(chan + d)*27 + tap];
        }
        if (tid < 32) ((float*)(sm + BS_OFF))[tid] = lb[chan + tid];
    }

    // ---------- Q fragments from gmem (scaled into log2 domain, hi/lo) ----------
    const int qb = wid * 32;              // each warp owns 32 q-rows
    uint32_t qh[2][2][4], ql[2][2][4];
    {
        const float sc = 0.17677669529663689f * 1.4426950408889634f;
        #pragma unroll
        for (int mt = 0; mt < 2; mt++){
            const int r0 = qb + mt*16 + (lane >> 2);
            const int r1 = r0 + 8;
            const int t0 = r0 >> 8, h0 = (r0 >> 2) & 63, w0 = r0 & 3;
            const int t1 = r1 >> 8, h1 = (r1 >> 2) & 63, w1 = r1 & 3;
            const float* p0 = qg + (size_t)(lbase + t0*4096 + h0*64 + w0)*Cc + chan;
            const float* p1 = qg + (size_t)(lbase + t1*4096 + h1*64 + w1)*Cc + chan;
            #pragma unroll
            for (int kt = 0; kt < 2; kt++){
                const int d0 = kt*16 + 2*(lane & 3);
                const float2 x0 = *(const float2*)(p0 + d0);
                const float2 x1 = *(const float2*)(p1 + d0);
                const float2 x2 = *(const float2*)(p0 + d0 + 8);
                const float2 x3 = *(const float2*)(p1 + d0 + 8);
                hilo2(x0.x*sc, x0.y*sc, qh[mt][kt][0], ql[mt][kt][0]);
                hilo2(x1.x*sc, x1.y*sc, qh[mt][kt][1], ql[mt][kt][1]);
                hilo2(x2.x*sc, x2.y*sc, qh[mt][kt][2], ql[mt][kt][2]);
                hilo2(x3.x*sc, x3.y*sc, qh[mt][kt][3], ql[mt][kt][3]);
            }
        }
    }
    __syncthreads();

    // ---------- mainloop: 32 subchunks of 16 keys, QK pipelined one chunk ahead ----------
    float oAcc[2][4][4];
    #pragma unroll
    for (int a = 0; a < 2; a++)
        #pragma unroll
        for (int b2 = 0; b2 < 4; b2++)
            #pragma unroll
            for (int c = 0; c < 4; c++) oAcc[a][b2][c] = 0.f;
    float ps[2][2] = {{0.f,0.f},{0.f,0.f}};

    const int lg = lane >> 3, lr = lane & 7;
    uint32_t kh[2][4], kl2[2][4];
    float s[2][2][4];

    // prologue: K(0) fragments + QK(0)
    #pragma unroll
    for (int nt = 0; nt < 2; nt++){
        const uint32_t a = smb + KH_OFF + kaddr(nt*8 + lr, lg);
        ldm4(kh[nt], a);
        ldm4(kl2[nt], a + (KL_OFF - KH_OFF));
    }
    #pragma unroll
    for (int mt = 0; mt < 2; mt++)
        #pragma unroll
        for (int nt = 0; nt < 2; nt++){
            float* sd = s[mt][nt];
            sd[0]=sd[1]=sd[2]=sd[3]=0.f;
            mma16816(sd, qh[mt][0], kh[nt][0], kh[nt][1]);
            mma16816(sd, qh[mt][1], kh[nt][2], kh[nt][3]);
            mma16816(sd, ql[mt][0], kh[nt][0], kh[nt][1]);
            mma16816(sd, ql[mt][1], kh[nt][2], kh[nt][3]);
            mma16816(sd, qh[mt][0], kl2[nt][0], kl2[nt][1]);
            mma16816(sd, qh[mt][1], kl2[nt][2], kl2[nt][3]);
        }

    #pragma unroll 1
    for (int cs = 0; cs < 32; cs++){
        const int j0 = cs * 16;

        // --- mt0: softmax on s[0] (produced by QK issued one iteration ago) ---
        float p0[8];
        #pragma unroll
        for (int i = 0; i < 4; i++){ p0[i] = ex2f(s[0][0][i]); p0[4+i] = ex2f(s[0][1][i]); }
        ps[0][0] += (p0[0]+p0[1]) + (p0[4]+p0[5]);
        ps[0][1] += (p0[2]+p0[3]) + (p0[6]+p0[7]);

        // V fragments for this chunk (independent -> overlaps tensor)
        uint32_t vh[2][4], vl[2][4];
        #pragma unroll
        for (int dg = 0; dg < 2; dg++){
            const int d  = dg*16 + (lg >> 1)*8 + lr;
            const int kc = (j0 >> 3) + (lg & 1);
            const uint32_t a = smb + VTH_OFF + vtaddr(d, kc);
            ldm4(vh[dg], a);
            ldm4(vl[dg], a + (VTL_OFF - VTH_OFF));
        }

        // mt0 pack + PV
        {
            uint32_t ah[4], al[4];
            hilo2(p0[0], p0[1], ah[0], al[0]);
            hilo2(p0[2], p0[3], ah[1], al[1]);
            hilo2(p0[4], p0[5], ah[2], al[2]);
            hilo2(p0[6], p0[7], ah[3], al[3]);
            #pragma unroll
            for (int ntd = 0; ntd < 4; ntd++){
                const int dg = ntd >> 1;
                const uint32_t b0 = vh[dg][(ntd&1)*2],  b1 = vh[dg][(ntd&1)*2+1];
                const uint32_t c0 = vl[dg][(ntd&1)*2],  c1 = vl[dg][(ntd&1)*2+1];
                float* od = oAcc[0][ntd];
                mma16816(od, ah, b0, b1);
                mma16816(od, al, b0, b1);
                mma16816(od, ah, c0, c1);
            }
        }

        // mt1 ex2 (frees all of s)
        float p1[8];
        #pragma unroll
        for (int i = 0; i < 4; i++){ p1[i] = ex2f(s[1][0][i]); p1[4+i] = ex2f(s[1][1][i]); }
        ps[1][0] += (p1[0]+p1[1]) + (p1[4]+p1[5]);
        ps[1][1] += (p1[2]+p1[3]) + (p1[6]+p1[7]);

        // prefetch K(cs+1) and issue QK(cs+1) into s (WAR-safe: ex2s issued above)
        if (cs < 31){
            const int j0n = j0 + 16;
            #pragma unroll
            for (int nt = 0; nt < 2; nt++){
                const uint32_t a = smb + KH_OFF + kaddr(j0n + nt*8 + lr, lg);
                ldm4(kh[nt], a);
                ldm4(kl2[nt], a + (KL_OFF - KH_OFF));
            }
            #pragma unroll
            for (int mt = 0; mt < 2; mt++)
                #pragma unroll
                for (int nt = 0; nt < 2; nt++){
                    float* sd = s[mt][nt];
                    sd[0]=sd[1]=sd[2]=sd[3]=0.f;
                    mma16816(sd, qh[mt][0], kh[nt][0], kh[nt][1]);
                    mma16816(sd, qh[mt][1], kh[nt][2], kh[nt][3]);
                    mma16816(sd, ql[mt][0], kh[nt][0], kh[nt][1]);
                    mma16816(sd, ql[mt][1], kh[nt][2], kh[nt][3]);
                    mma16816(sd, qh[mt][0], kl2[nt][0], kl2[nt][1]);
                    mma16816(sd, qh[mt][1], kl2[nt][2], kl2[nt][3]);
                }
        }

        // mt1 pack + PV
        {
            uint32_t ah[4], al[4];
            hilo2(p1[0], p1[1], ah[0], al[0]);
            hilo2(p1[2], p1[3], ah[1], al[1]);
            hilo2(p1[4], p1[5], ah[2], al[2]);
            hilo2(p1[6], p1[7], ah[3], al[3]);
            #pragma unroll
            for (int ntd = 0; ntd < 4; ntd++){
                const int dg = ntd >> 1;
                const uint32_t b0 = vh[dg][(ntd&1)*2],  b1 = vh[dg][(ntd&1)*2+1];
                const uint32_t c0 = vl[dg][(ntd&1)*2],  c1 = vl[dg][(ntd&1)*2+1];
                float* od = oAcc[1][ntd];
                mma16816(od, ah, b0, b1);
                mma16816(od, al, b0, b1);
                mma16816(od, ah, c0, c1);
            }
        }
    }

    // ---------- row sums (4-lane bfly), normalize, stage O to smem ----------
    #pragma unroll
    for (int mt = 0; mt < 2; mt++)
        #pragma unroll
        for (int h2 = 0; h2 < 2; h2++){
            float v = ps[mt][h2];
            v += __shfl_xor_sync(0xffffffffu, v, 1);
            v += __shfl_xor_sync(0xffffffffu, v, 2);
            ps[mt][h2] = 1.f / v;
        }
    __syncthreads();   // everyone done reading K/VT smem
    #pragma unroll
    for (int mt = 0; mt < 2; mt++){
        const int r0 = qb + mt*16 + (lane >> 2);
        #pragma unroll
        for (int ntd = 0; ntd < 4; ntd++){
            const int cc = ntd*8 + 2*(lane & 3);
            float2 a, b2;
            a.x  = oAcc[mt][ntd][0] * ps[mt][0];
            a.y  = oAcc[mt][ntd][1] * ps[mt][0];
            b2.x = oAcc[mt][ntd][2] * ps[mt][1];
            b2.y = oAcc[mt][ntd][3] * ps[mt][1];
            *(float2*)(sm + OS_OFF + r0*144 + cc*4)      = a;
            *(float2*)(sm + OS_OFF + (r0+8)*144 + cc*4)  = b2;
        }
    }
    __syncthreads();

    // ---------- epilogue: LePE conv (fp32 V) + bias + store ----------
    const float* Vs  = (const float*)(sm + VF_OFF);
    const float* Wsm = (const float*)(sm + WS_OFF);
    const float* Bsm = (const float*)(sm + BS_OFF);

    {
        const int n = tid;                 // one row per thread
        float o[32];
        #pragma unroll
        for (int v = 0; v < 8; v++){
            const float4 f = *(const float4*)(sm + OS_OFF + n*144 + v*16);
            o[4*v+0] = f.x; o[4*v+1] = f.y; o[4*v+2] = f.z; o[4*v+3] = f.w;
        }
        const int rt = n >> 8, rh = (n >> 2) & 63, rws = n & 3;
        #pragma unroll
        for (int dt = -1; dt <= 1; dt++){
            const int tt = rt + dt;
            if ((unsigned)tt >= 2u) continue;
            #pragma unroll
            for (int dh = -1; dh <= 1; dh++){
                const int hh = rh + dh;
                if ((unsigned)hh >= 64u) continue;
                #pragma unroll
                for (int dw = -1; dw <= 1; dw++){
                    const int ww2 = rws + dw;
                    if ((unsigned)ww2 >= 4u) continue;
                    const int n2  = tt*256 + hh*4 + ww2;
                    const int tap = (dt+1)*9 + (dh+1)*3 + (dw+1);
                    const float* vr = Vs + n2*36;
                    const float* wr = Wsm + tap*32;
                    #pragma unroll
                    for (int i = 0; i < 32; i++) o[i] += wr[i]*vr[i];
                }
            }
        }
        const size_t l = (size_t)(lbase + rt*4096 + rh*64 + rws);
        float* op = out + batch_off + l*Cc + chan;
        #pragma unroll
        for (int v = 0; v < 8; v++){
            float4 r4;
            r4.x = o[4*v+0] + Bsm[4*v+0];
            r4.y = o[4*v+1] + Bsm[4*v+1];
            r4.z = o[4*v+2] + Bsm[4*v+2];
            r4.w = o[4*v+3] + Bsm[4*v+3];
            ((float4*)op)[v] = r4;
        }
    }
}

extern "C" void kernel_launch(void* const* d_in, const int* in_sizes, int n_in,
                              void* d_out, int out_size)
{
    const float* qkv = (const float*)d_in[0];
    const float* lw  = (const float*)d_in[1];
    const float* lb  = (const float*)d_in[2];
    float* out       = (float*)d_out;

    cudaFuncSetAttribute(lepe_hmma, cudaFuncAttributeMaxDynamicSharedMemorySize, SMEM_BYTES);
    lepe_hmma<<<512, 512, SMEM_BYTES>>>(qkv, lw, lb, out);
}

// round 8
// speedup vs baseline: 1.6641x; 1.6641x over previous
#include <cuda_runtime.h>
#include <cuda_fp16.h>
#include <cstdint>

#define Bb 2
#define Ll 32768
#define Cc 128
#define NTOK 512
#define HD 32

// ---- smem byte offsets ----
#define KF_OFF  0           // K fp16: 512 rows x 64B (swizzled)    32768
#define VT_OFF  32768       // V^T fp16: 32 d-rows x 1024B (swz)    32768
#define VF_OFF  65536       // V fp32 [512][36]                     73728
#define OS_OFF  139264      // O fp32 [512][36] staging             73728
#define WS_OFF  212992      // weights [27][32] f32                  3456
#define BS_OFF  216448      // bias [32] f32                          128
#define SMEM_BYTES 216576

static __device__ __forceinline__ float ex2f(float x){
    float y; asm("ex2.approx.ftz.f32 %0, %1;" : "=f"(y) : "f"(x)); return y;
}
static __device__ __forceinline__ uint32_t s2u(const void* p){
    uint32_t a;
    asm("{ .reg .u64 t; cvta.to.shared.u64 t, %1; cvt.u32.u64 %0, t; }" : "=r"(a) : "l"(p));
    return a;
}
// pack two f32 -> f16x2 (a -> low half, b -> high half)
static __device__ __forceinline__ uint32_t pk2h(float a, float b){
    uint32_t r; asm("cvt.rn.f16x2.f32 %0, %1, %2;" : "=r"(r) : "f"(b), "f"(a)); return r;
}
static __device__ __forceinline__ void ldm4(uint32_t* r, uint32_t a){
    asm volatile("ldmatrix.sync.aligned.m8n8.x4.shared.b16 {%0,%1,%2,%3}, [%4];"
        : "=r"(r[0]), "=r"(r[1]), "=r"(r[2]), "=r"(r[3]) : "r"(a));
}
static __device__ __forceinline__ void mma16816(float* d, const uint32_t* a, uint32_t b0, uint32_t b1){
    asm volatile("mma.sync.aligned.m16n8k16.row.col.f32.f16.f16.f32 "
        "{%0,%1,%2,%3},{%4,%5,%6,%7},{%8,%9},{%0,%1,%2,%3};"
        : "+f"(d[0]), "+f"(d[1]), "+f"(d[2]), "+f"(d[3])
        : "r"(a[0]), "r"(a[1]), "r"(a[2]), "r"(a[3]), "r"(b0), "r"(b1));
}
static __device__ __forceinline__ void sts_u16(uint32_t a, uint32_t v){
    asm volatile("st.shared.u16 [%0], %1;" :: "r"(a), "h"((unsigned short)v) : "memory");
}
static __device__ __forceinline__ void sts_v4(uint32_t a, uint32_t x, uint32_t y, uint32_t z, uint32_t w){
    asm volatile("st.shared.v4.b32 [%0], {%1,%2,%3,%4};" :: "r"(a), "r"(x), "r"(y), "r"(z), "r"(w) : "memory");
}
// K row addressing: 64B rows; 16B-chunk c rotated by (row>>1) so ldmatrix (8 rows, fixed c) is conflict-free
static __device__ __forceinline__ uint32_t kaddr(int n, int c){
    return (uint32_t)n*64u + ((((uint32_t)c + ((uint32_t)n >> 1)) & 3u) * 16u);
}
// V^T addressing: 1024B d-rows; low 3 bits of key-chunk XOR d
static __device__ __forceinline__ uint32_t vtaddr(int d, int kc){
    uint32_t sw = ((uint32_t)kc & ~7u) | (((uint32_t)(kc ^ d)) & 7u);
    return (uint32_t)d*1024u + sw*16u;
}

__global__ void __launch_bounds__(512, 1)
lepe_hmma(const float* __restrict__ qkv,
          const float* __restrict__ lw,
          const float* __restrict__ lb,
          float* __restrict__ out)
{
    extern __shared__ char sm[];
    const uint32_t smb = s2u(sm);
    const int tid = threadIdx.x;
    const int wid = tid >> 5, lane = tid & 31;

    const int bx = blockIdx.x;            // (window, head)
    const int win = bx >> 2, head = bx & 3;
    const int b  = win >> 6;
    const int tB = (win >> 4) & 3;
    const int wB = win & 15;
    const size_t batch_off = (size_t)b * Ll * Cc;
    const int chan  = head * HD;
    const int lbase = tB*8192 + wB*4;

    const float* qg = qkv + batch_off;
    const float* kg = qkv + (size_t)1*Bb*Ll*Cc + batch_off;
    const float* vg = qkv + (size_t)2*Bb*Ll*Cc + batch_off;

    // ---------- stage K fp16, V^T fp16, V fp32 ----------
    {
        const int q = tid & 3;            // 4 threads per row, 8 d-values each
        const int rbase = tid >> 2;       // 0..127
        for (int it = 0; it < 4; it++){
            const int j = it*128 + rbase;
            const int t = j >> 8, h = (j >> 2) & 63, ws = j & 3;
            const size_t l = (size_t)(lbase + t*4096 + h*64 + ws);
            const float4 k0 = *(const float4*)(kg + l*Cc + chan + q*8);
            const float4 k1 = *(const float4*)(kg + l*Cc + chan + q*8 + 4);
            sts_v4(smb + KF_OFF + kaddr(j, q),
                   pk2h(k0.x, k0.y), pk2h(k0.z, k0.w),
                   pk2h(k1.x, k1.y), pk2h(k1.z, k1.w));

            const float4 v0 = *(const float4*)(vg + l*Cc + chan + q*8);
            const float4 v1 = *(const float4*)(vg + l*Cc + chan + q*8 + 4);
            *(float4*)(sm + VF_OFF + j*144 + q*32)      = v0;
            *(float4*)(sm + VF_OFF + j*144 + q*32 + 16) = v1;
            uint32_t hh[4];
            hh[0] = pk2h(v0.x, v0.y); hh[1] = pk2h(v0.z, v0.w);
            hh[2] = pk2h(v1.x, v1.y); hh[3] = pk2h(v1.z, v1.w);
            const int kc = j >> 3;
            const uint32_t ko = (uint32_t)(j & 7) * 2u;
            #pragma unroll
            for (int e = 0; e < 8; e++){
                const int d = q*8 + e;
                const uint32_t hb = (e & 1) ? (hh[e>>1] >> 16) : (hh[e>>1] & 0xffffu);
                sts_u16(smb + VT_OFF + vtaddr(d, kc) + ko, hb);
            }
        }
        for (int idx = tid; idx < 27*32; idx += 512){
            const int tap = idx >> 5, d = idx & 31;
            ((float*)(sm + WS_OFF))[tap*32 + d] = lw[(chan + d)*27 + tap];
        }
        if (tid < 32) ((float*)(sm + BS_OFF))[tid] = lb[chan + tid];
    }

    // ---------- Q fragments from gmem (scaled into log2 domain, fp16) ----------
    const int qb = wid * 32;              // each warp owns 32 q-rows
    uint32_t qf[2][2][4];
    {
        const float sc = 0.17677669529663689f * 1.4426950408889634f;
        #pragma unroll
        for (int mt = 0; mt < 2; mt++){
            const int r0 = qb + mt*16 + (lane >> 2);
            const int r1 = r0 + 8;
            const int t0 = r0 >> 8, h0 = (r0 >> 2) & 63, w0 = r0 & 3;
            const int t1 = r1 >> 8, h1 = (r1 >> 2) & 63, w1 = r1 & 3;
            const float* p0 = qg + (size_t)(lbase + t0*4096 + h0*64 + w0)*Cc + chan;
            const float* p1 = qg + (size_t)(lbase + t1*4096 + h1*64 + w1)*Cc + chan;
            #pragma unroll
            for (int kt = 0; kt < 2; kt++){
                const int d0 = kt*16 + 2*(lane & 3);
                const float2 x0 = *(const float2*)(p0 + d0);
                const float2 x1 = *(const float2*)(p1 + d0);
                const float2 x2 = *(const float2*)(p0 + d0 + 8);
                const float2 x3 = *(const float2*)(p1 + d0 + 8);
                qf[mt][kt][0] = pk2h(x0.x*sc, x0.y*sc);
                qf[mt][kt][1] = pk2h(x1.x*sc, x1.y*sc);
                qf[mt][kt][2] = pk2h(x2.x*sc, x2.y*sc);
                qf[mt][kt][3] = pk2h(x3.x*sc, x3.y*sc);
            }
        }
    }
    __syncthreads();

    // ---------- mainloop: 32 subchunks of 16 keys ----------
    float oAcc[2][4][4];
    #pragma unroll
    for (int a = 0; a < 2; a++)
        #pragma unroll
        for (int b2 = 0; b2 < 4; b2++)
            #pragma unroll
            for (int c = 0; c < 4; c++) oAcc[a][b2][c] = 0.f;
    float ps[2][2] = {{0.f,0.f},{0.f,0.f}};

    const int lg = lane >> 3, lr = lane & 7;
    #pragma unroll 1
    for (int cs = 0; cs < 32; cs++){
        const int j0 = cs * 16;
        // V fragments (independent -> overlaps tensor)
        uint32_t vh[2][4];
        #pragma unroll
        for (int dg = 0; dg < 2; dg++){
            const int d  = dg*16 + (lg >> 1)*8 + lr;
            const int kc = (j0 >> 3) + (lg & 1);
            ldm4(vh[dg], smb + VT_OFF + vtaddr(d, kc));
        }
        // K fragments (B operand for QK): tiles [8 keys x 8 d]
        uint32_t kh[2][4];
        #pragma unroll
        for (int nt = 0; nt < 2; nt++)
            ldm4(kh[nt], smb + KF_OFF + kaddr(j0 + nt*8 + lr, lg));
        // S = Q K^T (single fp16 term)
        float s[2][2][4];
        #pragma unroll
        for (int mt = 0; mt < 2; mt++)
            #pragma unroll
            for (int nt = 0; nt < 2; nt++){
                float* sd = s[mt][nt];
                sd[0]=sd[1]=sd[2]=sd[3]=0.f;
                mma16816(sd, qf[mt][0], kh[nt][0], kh[nt][1]);
                mma16816(sd, qf[mt][1], kh[nt][2], kh[nt][3]);
            }
        // softmax + register repack (C->A) + PV
        #pragma unroll
        for (int mt = 0; mt < 2; mt++){
            float p0[8];
            #pragma unroll
            for (int i = 0; i < 4; i++){ p0[i] = ex2f(s[mt][0][i]); p0[4+i] = ex2f(s[mt][1][i]); }
            ps[mt][0] += (p0[0]+p0[1]) + (p0[4]+p0[5]);
            ps[mt][1] += (p0[2]+p0[3]) + (p0[6]+p0[7]);
            uint32_t ah[4];
            ah[0] = pk2h(p0[0], p0[1]);
            ah[1] = pk2h(p0[2], p0[3]);
            ah[2] = pk2h(p0[4], p0[5]);
            ah[3] = pk2h(p0[6], p0[7]);
            #pragma unroll
            for (int ntd = 0; ntd < 4; ntd++){
                const int dg = ntd >> 1;
                mma16816(oAcc[mt][ntd], ah, vh[dg][(ntd&1)*2], vh[dg][(ntd&1)*2+1]);
            }
        }
    }

    // ---------- row sums (4-lane bfly), normalize, stage O to smem ----------
    #pragma unroll
    for (int mt = 0; mt < 2; mt++)
        #pragma unroll
        for (int h2 = 0; h2 < 2; h2++){
            float v = ps[mt][h2];
            v += __shfl_xor_sync(0xffffffffu, v, 1);
            v += __shfl_xor_sync(0xffffffffu, v, 2);
            ps[mt][h2] = 1.f / v;
        }
    #pragma unroll
    for (int mt = 0; mt < 2; mt++){
        const int r0 = qb + mt*16 + (lane >> 2);
        #pragma unroll
        for (int ntd = 0; ntd < 4; ntd++){
            const int cc = ntd*8 + 2*(lane & 3);
            float2 a, b2;
            a.x  = oAcc[mt][ntd][0] * ps[mt][0];
            a.y  = oAcc[mt][ntd][1] * ps[mt][0];
            b2.x = oAcc[mt][ntd][2] * ps[mt][1];
            b2.y = oAcc[mt][ntd][3] * ps[mt][1];
            *(float2*)(sm + OS_OFF + r0*144 + cc*4)      = a;
            *(float2*)(sm + OS_OFF + (r0+8)*144 + cc*4)  = b2;
        }
    }
    __syncthreads();

    // ---------- epilogue: LePE conv (fp32 V) + bias + store ----------
    const float* Vs  = (const float*)(sm + VF_OFF);
    const float* Wsm = (const float*)(sm + WS_OFF);
    const float* Bsm = (const float*)(sm + BS_OFF);

    {
        const int n = tid;                 // one row per thread
        float o[32];
        #pragma unroll
        for (int v = 0; v < 8; v++){
            const float4 f = *(const float4*)(sm + OS_OFF + n*144 + v*16);
            o[4*v+0] = f.x; o[4*v+1] = f.y; o[4*v+2] = f.z; o[4*v+3] = f.w;
        }
        const int rt = n >> 8, rh = (n >> 2) & 63, rws = n & 3;
        #pragma unroll
        for (int dt = -1; dt <= 1; dt++){
            const int tt = rt + dt;
            if ((unsigned)tt >= 2u) continue;
            #pragma unroll
            for (int dh = -1; dh <= 1; dh++){
                const int hh = rh + dh;
                if ((unsigned)hh >= 64u) continue;
                #pragma unroll
                for (int dw = -1; dw <= 1; dw++){
                    const int ww2 = rws + dw;
                    if ((unsigned)ww2 >= 4u) continue;
                    const int n2  = tt*256 + hh*4 + ww2;
                    const int tap = (dt+1)*9 + (dh+1)*3 + (dw+1);
                    const float* vr = Vs + n2*36;
                    const float* wr = Wsm + tap*32;
                    #pragma unroll
                    for (int i = 0; i < 32; i++) o[i] += wr[i]*vr[i];
                }
            }
        }
        const size_t l = (size_t)(lbase + rt*4096 + rh*64 + rws);
        float* op = out + batch_off + l*Cc + chan;
        #pragma unroll
        for (int v = 0; v < 8; v++){
            float4 r4;
            r4.x = o[4*v+0] + Bsm[4*v+0];
            r4.y = o[4*v+1] + Bsm[4*v+1];
            r4.z = o[4*v+2] + Bsm[4*v+2];
            r4.w = o[4*v+3] + Bsm[4*v+3];
            ((float4*)op)[v] = r4;
        }
    }
}

extern "C" void kernel_launch(void* const* d_in, const int* in_sizes, int n_in,
                              void* d_out, int out_size)
{
    const float* qkv = (const float*)d_in[0];
    const float* lw  = (const float*)d_in[1];
    const float* lb  = (const float*)d_in[2];
    float* out       = (float*)d_out;

    cudaFuncSetAttribute(lepe_hmma, cudaFuncAttributeMaxDynamicSharedMemorySize, SMEM_BYTES);
    lepe_hmma<<<512, 512, SMEM_BYTES>>>(qkv, lw, lb, out);
}

// round 9
// speedup vs baseline: 2.0595x; 1.2376x over previous
#include <cuda_runtime.h>
#include <cuda_fp16.h>
#include <cstdint>

#define Bb 2
#define Ll 32768
#define Cc 128
#define NTOK 512
#define HD 32

// ---- smem byte offsets ----
#define KF_OFF  0           // K fp16: 512 rows x 64B (swizzled)      32768
#define VH_OFF  32768       // V fp16 row-major: 512 rows x 80B       40960
#define OS_OFF  73728       // O fp32 [512][36] staging               73728
#define WS_OFF  147456      // weights [27][32] f32                    3456
#define BS_OFF  150912      // bias [32] f32                            128
#define SMEM_BYTES 151040

static __device__ __forceinline__ float ex2f(float x){
    float y; asm("ex2.approx.ftz.f32 %0, %1;" : "=f"(y) : "f"(x)); return y;
}
static __device__ __forceinline__ uint32_t s2u(const void* p){
    uint32_t a;
    asm("{ .reg .u64 t; cvta.to.shared.u64 t, %1; cvt.u32.u64 %0, t; }" : "=r"(a) : "l"(p));
    return a;
}
// pack two f32 -> f16x2 (a -> low half, b -> high half)
static __device__ __forceinline__ uint32_t pk2h(float a, float b){
    uint32_t r; asm("cvt.rn.f16x2.f32 %0, %1, %2;" : "=r"(r) : "f"(b), "f"(a)); return r;
}
static __device__ __forceinline__ void ldm4(uint32_t* r, uint32_t a){
    asm volatile("ldmatrix.sync.aligned.m8n8.x4.shared.b16 {%0,%1,%2,%3}, [%4];"
        : "=r"(r[0]), "=r"(r[1]), "=r"(r[2]), "=r"(r[3]) : "r"(a));
}
static __device__ __forceinline__ void ldm4t(uint32_t* r, uint32_t a){
    asm volatile("ldmatrix.sync.aligned.m8n8.x4.trans.shared.b16 {%0,%1,%2,%3}, [%4];"
        : "=r"(r[0]), "=r"(r[1]), "=r"(r[2]), "=r"(r[3]) : "r"(a));
}
static __device__ __forceinline__ void mma16816(float* d, const uint32_t* a, uint32_t b0, uint32_t b1){
    asm volatile("mma.sync.aligned.m16n8k16.row.col.f32.f16.f16.f32 "
        "{%0,%1,%2,%3},{%4,%5,%6,%7},{%8,%9},{%0,%1,%2,%3};"
        : "+f"(d[0]), "+f"(d[1]), "+f"(d[2]), "+f"(d[3])
        : "r"(a[0]), "r"(a[1]), "r"(a[2]), "r"(a[3]), "r"(b0), "r"(b1));
}
static __device__ __forceinline__ void sts_v4(uint32_t a, uint32_t x, uint32_t y, uint32_t z, uint32_t w){
    asm volatile("st.shared.v4.b32 [%0], {%1,%2,%3,%4};" :: "r"(a), "r"(x), "r"(y), "r"(z), "r"(w) : "memory");
}
static __device__ __forceinline__ void lds_v4(uint32_t* r, uint32_t a){
    asm volatile("ld.shared.v4.b32 {%0,%1,%2,%3}, [%4];"
        : "=r"(r[0]), "=r"(r[1]), "=r"(r[2]), "=r"(r[3]) : "r"(a));
}
// K row addressing: 64B rows; 16B-chunk c rotated by (row>>1) so ldmatrix (8 rows, fixed c) is conflict-free
static __device__ __forceinline__ uint32_t kaddr(int n, int c){
    return (uint32_t)n*64u + ((((uint32_t)c + ((uint32_t)n >> 1)) & 3u) * 16u);
}

__global__ void __launch_bounds__(512, 1)
lepe_hmma(const float* __restrict__ qkv,
          const float* __restrict__ lw,
          const float* __restrict__ lb,
          float* __restrict__ out)
{
    extern __shared__ char sm[];
    const uint32_t smb = s2u(sm);
    const int tid = threadIdx.x;
    const int wid = tid >> 5, lane = tid & 31;

    const int bx = blockIdx.x;            // (window, head)
    const int win = bx >> 2, head = bx & 3;
    const int b  = win >> 6;
    const int tB = (win >> 4) & 3;
    const int wB = win & 15;
    const size_t batch_off = (size_t)b * Ll * Cc;
    const int chan  = head * HD;
    const int lbase = tB*8192 + wB*4;

    const float* qg = qkv + batch_off;
    const float* kg = qkv + (size_t)1*Bb*Ll*Cc + batch_off;
    const float* vg = qkv + (size_t)2*Bb*Ll*Cc + batch_off;

    // ---------- stage K fp16 (swizzled), V fp16 row-major ----------
    {
        const int q = tid & 3;            // 4 threads per row, 8 d-values each
        const int rbase = tid >> 2;       // 0..127
        for (int it = 0; it < 4; it++){
            const int j = it*128 + rbase;
            const int t = j >> 8, h = (j >> 2) & 63, ws = j & 3;
            const size_t l = (size_t)(lbase + t*4096 + h*64 + ws);
            const float4 k0 = *(const float4*)(kg + l*Cc + chan + q*8);
            const float4 k1 = *(const float4*)(kg + l*Cc + chan + q*8 + 4);
            sts_v4(smb + KF_OFF + kaddr(j, q),
                   pk2h(k0.x, k0.y), pk2h(k0.z, k0.w),
                   pk2h(k1.x, k1.y), pk2h(k1.z, k1.w));

            const float4 v0 = *(const float4*)(vg + l*Cc + chan + q*8);
            const float4 v1 = *(const float4*)(vg + l*Cc + chan + q*8 + 4);
            sts_v4(smb + VH_OFF + (uint32_t)j*80u + (uint32_t)q*16u,
                   pk2h(v0.x, v0.y), pk2h(v0.z, v0.w),
                   pk2h(v1.x, v1.y), pk2h(v1.z, v1.w));
        }
        for (int idx = tid; idx < 27*32; idx += 512){
            const int tap = idx >> 5, d = idx & 31;
            ((float*)(sm + WS_OFF))[tap*32 + d] = lw[(chan + d)*27 + tap];
        }
        if (tid < 32) ((float*)(sm + BS_OFF))[tid] = lb[chan + tid];
    }

    // ---------- Q fragments from gmem (scaled into log2 domain, fp16) ----------
    const int qb = wid * 32;              // each warp owns 32 q-rows
    uint32_t qf[2][2][4];
    {
        const float sc = 0.17677669529663689f * 1.4426950408889634f;
        #pragma unroll
        for (int mt = 0; mt < 2; mt++){
            const int r0 = qb + mt*16 + (lane >> 2);
            const int r1 = r0 + 8;
            const int t0 = r0 >> 8, h0 = (r0 >> 2) & 63, w0 = r0 & 3;
            const int t1 = r1 >> 8, h1 = (r1 >> 2) & 63, w1 = r1 & 3;
            const float* p0 = qg + (size_t)(lbase + t0*4096 + h0*64 + w0)*Cc + chan;
            const float* p1 = qg + (size_t)(lbase + t1*4096 + h1*64 + w1)*Cc + chan;
            #pragma unroll
            for (int kt = 0; kt < 2; kt++){
                const int d0 = kt*16 + 2*(lane & 3);
                const float2 x0 = *(const float2*)(p0 + d0);
                const float2 x1 = *(const float2*)(p1 + d0);
                const float2 x2 = *(const float2*)(p0 + d0 + 8);
                const float2 x3 = *(const float2*)(p1 + d0 + 8);
                qf[mt][kt][0] = pk2h(x0.x*sc, x0.y*sc);
                qf[mt][kt][1] = pk2h(x1.x*sc, x1.y*sc);
                qf[mt][kt][2] = pk2h(x2.x*sc, x2.y*sc);
                qf[mt][kt][3] = pk2h(x3.x*sc, x3.y*sc);
            }
        }
    }
    __syncthreads();

    // ---------- mainloop: 32 subchunks of 16 keys ----------
    float oAcc[2][4][4];
    #pragma unroll
    for (int a = 0; a < 2; a++)
        #pragma unroll
        for (int b2 = 0; b2 < 4; b2++)
            #pragma unroll
            for (int c = 0; c < 4; c++) oAcc[a][b2][c] = 0.f;
    float ps[2][2] = {{0.f,0.f},{0.f,0.f}};

    const int lg = lane >> 3, lr = lane & 7;
    #pragma unroll 1
    for (int cs = 0; cs < 32; cs++){
        const int j0 = cs * 16;
        // V fragments via ldmatrix.trans from row-major fp16 V
        // group g: keys j0+(g&1)*8+lr, d-chunk dg*16 + (g>>1)*8
        uint32_t vh[2][4];
        #pragma unroll
        for (int dg = 0; dg < 2; dg++){
            const uint32_t a = smb + VH_OFF
                + (uint32_t)(j0 + (lg & 1)*8 + lr)*80u
                + (uint32_t)dg*32u + (uint32_t)(lg >> 1)*16u;
            ldm4t(vh[dg], a);
        }
        // K fragments (B operand for QK): tiles [8 keys x 8 d]
        uint32_t kh[2][4];
        #pragma unroll
        for (int nt = 0; nt < 2; nt++)
            ldm4(kh[nt], smb + KF_OFF + kaddr(j0 + nt*8 + lr, lg));
        // S = Q K^T (single fp16 term)
        float s[2][2][4];
        #pragma unroll
        for (int mt = 0; mt < 2; mt++)
            #pragma unroll
            for (int nt = 0; nt < 2; nt++){
                float* sd = s[mt][nt];
                sd[0]=sd[1]=sd[2]=sd[3]=0.f;
                mma16816(sd, qf[mt][0], kh[nt][0], kh[nt][1]);
                mma16816(sd, qf[mt][1], kh[nt][2], kh[nt][3]);
            }
        // softmax + register repack (C->A) + PV
        #pragma unroll
        for (int mt = 0; mt < 2; mt++){
            float p0[8];
            #pragma unroll
            for (int i = 0; i < 4; i++){ p0[i] = ex2f(s[mt][0][i]); p0[4+i] = ex2f(s[mt][1][i]); }
            ps[mt][0] += (p0[0]+p0[1]) + (p0[4]+p0[5]);
            ps[mt][1] += (p0[2]+p0[3]) + (p0[6]+p0[7]);
            uint32_t ah[4];
            ah[0] = pk2h(p0[0], p0[1]);
            ah[1] = pk2h(p0[2], p0[3]);
            ah[2] = pk2h(p0[4], p0[5]);
            ah[3] = pk2h(p0[6], p0[7]);
            #pragma unroll
            for (int ntd = 0; ntd < 4; ntd++){
                const int dg = ntd >> 1;
                mma16816(oAcc[mt][ntd], ah, vh[dg][(ntd&1)*2], vh[dg][(ntd&1)*2+1]);
            }
        }
    }

    // ---------- row sums (4-lane bfly), normalize, stage O to smem ----------
    #pragma unroll
    for (int mt = 0; mt < 2; mt++)
        #pragma unroll
        for (int h2 = 0; h2 < 2; h2++){
            float v = ps[mt][h2];
            v += __shfl_xor_sync(0xffffffffu, v, 1);
            v += __shfl_xor_sync(0xffffffffu, v, 2);
            ps[mt][h2] = 1.f / v;
        }
    #pragma unroll
    for (int mt = 0; mt < 2; mt++){
        const int r0 = qb + mt*16 + (lane >> 2);
        #pragma unroll
        for (int ntd = 0; ntd < 4; ntd++){
            const int cc = ntd*8 + 2*(lane & 3);
            float2 a, b2;
            a.x  = oAcc[mt][ntd][0] * ps[mt][0];
            a.y  = oAcc[mt][ntd][1] * ps[mt][0];
            b2.x = oAcc[mt][ntd][2] * ps[mt][1];
            b2.y = oAcc[mt][ntd][3] * ps[mt][1];
            *(float2*)(sm + OS_OFF + r0*144 + cc*4)      = a;
            *(float2*)(sm + OS_OFF + (r0+8)*144 + cc*4)  = b2;
        }
    }
    __syncthreads();

    // ---------- epilogue: t-paired LePE conv (fp16 V) + bias + store ----------
    // thread = (row r in t0-plane, channel-half); handles rows r (t=0) and r+256 (t=1)
    {
        const int r    = tid & 255;
        const int half = tid >> 8;
        const int c0   = half * 16;
        const float* Wsm = (const float*)(sm + WS_OFF);
        const float* Bsm = (const float*)(sm + BS_OFF);

        float o0[16], o1[16];
        #pragma unroll
        for (int k = 0; k < 4; k++){
            const float4 f0 = *(const float4*)(sm + OS_OFF + r*144       + c0*4 + k*16);
            const float4 f1 = *(const float4*)(sm + OS_OFF + (r+256)*144 + c0*4 + k*16);
            o0[4*k+0]=f0.x; o0[4*k+1]=f0.y; o0[4*k+2]=f0.z; o0[4*k+3]=f0.w;
            o1[4*k+0]=f1.x; o1[4*k+1]=f1.y; o1[4*k+2]=f1.z; o1[4*k+3]=f1.w;
        }
        const int rh = (r >> 2) & 63, rws = r & 3;
        #pragma unroll
        for (int dh = -1; dh <= 1; dh++){
            const int hh = rh + dh;
            if ((unsigned)hh >= 64u) continue;
            #pragma unroll
            for (int dw = -1; dw <= 1; dw++){
                const int ww2 = rws + dw;
                if ((unsigned)ww2 >= 4u) continue;
                const int n2 = hh*4 + ww2;
                uint32_t v0p[8], v1p[8];
                const uint32_t a0 = smb + VH_OFF + (uint32_t)n2*80u + (uint32_t)c0*2u;
                lds_v4(v0p,     a0);
                lds_v4(v0p + 4, a0 + 16u);
                lds_v4(v1p,     a0 + 256u*80u);
                lds_v4(v1p + 4, a0 + 256u*80u + 16u);
                const int wb = (dh+1)*3 + (dw+1);
                const float* w0 = Wsm + (     wb)*32 + c0;   // dt=-1 tap (for row t1 from v(t0))
                const float* w1 = Wsm + ( 9 + wb)*32 + c0;   // dt= 0 tap
                const float* w2 = Wsm + (18 + wb)*32 + c0;   // dt=+1 tap (for row t0 from v(t1))
                #pragma unroll
                for (int i = 0; i < 8; i++){
                    const float2 x0 = __half22float2(*reinterpret_cast<const __half2*>(&v0p[i]));
                    const float2 x1 = __half22float2(*reinterpret_cast<const __half2*>(&v1p[i]));
                    o0[2*i]   += w1[2*i]*x0.x   + w2[2*i]*x1.x;
                    o0[2*i+1] += w1[2*i+1]*x0.y + w2[2*i+1]*x1.y;
                    o1[2*i]   += w0[2*i]*x0.x   + w1[2*i]*x1.x;
                    o1[2*i+1] += w0[2*i+1]*x0.y + w1[2*i+1]*x1.y;
                }
            }
        }
        const size_t l0 = (size_t)(lbase +        rh*64 + rws);
        const size_t l1 = (size_t)(lbase + 4096 + rh*64 + rws);
        float* op0 = out + batch_off + l0*Cc + chan + c0;
        float* op1 = out + batch_off + l1*Cc + chan + c0;
        #pragma unroll
        for (int k = 0; k < 4; k++){
            float4 r4;
            r4.x = o0[4*k+0] + Bsm[c0+4*k+0];
            r4.y = o0[4*k+1] + Bsm[c0+4*k+1];
            r4.z = o0[4*k+2] + Bsm[c0+4*k+2];
            r4.w = o0[4*k+3] + Bsm[c0+4*k+3];
            ((float4*)op0)[k] = r4;
            r4.x = o1[4*k+0] + Bsm[c0+4*k+0];
            r4.y = o1[4*k+1] + Bsm[c0+4*k+1];
            r4.z = o1[4*k+2] + Bsm[c0+4*k+2];
            r4.w = o1[4*k+3] + Bsm[c0+4*k+3];
            ((float4*)op1)[k] = r4;
        }
    }
}

extern "C" void kernel_launch(void* const* d_in, const int* in_sizes, int n_in,
                              void* d_out, int out_size)
{
    const float* qkv = (const float*)d_in[0];
    const float* lw  = (const float*)d_in[1];
    const float* lb  = (const float*)d_in[2];
    float* out       = (float*)d_out;

    cudaFuncSetAttribute(lepe_hmma, cudaFuncAttributeMaxDynamicSharedMemorySize, SMEM_BYTES);
    lepe_hmma<<<512, 512, SMEM_BYTES>>>(qkv, lw, lb, out);
}

// round 10
// speedup vs baseline: 2.0615x; 1.0010x over previous
#include <cuda_runtime.h>
#include <cuda_fp16.h>
#include <cstdint>

#define Bb 2
#define Ll 32768
#define Cc 128
#define NTOK 512
#define HD 32

// ---- smem byte offsets ----
#define KF_OFF  0           // K fp16: 512 rows x 64B (swizzled)      32768
#define VH_OFF  32768       // V fp16 row-major: 512 rows x 80B       40960
                            //   (halves 32..39 = pad: d32=1.0, rest 0 -> tensor row-sums)
#define OS_OFF  73728       // O fp32 [512][36] staging               73728
#define WS_OFF  147456      // weights [27][32] f32                    3456
#define BS_OFF  150912      // bias [32] f32                            128
#define SMEM_BYTES 151040

static __device__ __forceinline__ uint32_t s2u(const void* p){
    uint32_t a;
    asm("{ .reg .u64 t; cvta.to.shared.u64 t, %1; cvt.u32.u64 %0, t; }" : "=r"(a) : "l"(p));
    return a;
}
// pack two f32 -> f16x2 (a -> low half, b -> high half)
static __device__ __forceinline__ uint32_t pk2h(float a, float b){
    uint32_t r; asm("cvt.rn.f16x2.f32 %0, %1, %2;" : "=r"(r) : "f"(b), "f"(a)); return r;
}
static __device__ __forceinline__ uint32_t ex2h2(uint32_t a){
    uint32_t r; asm("ex2.approx.f16x2 %0, %1;" : "=r"(r) : "r"(a)); return r;
}
static __device__ __forceinline__ void ldm4(uint32_t* r, uint32_t a){
    asm volatile("ldmatrix.sync.aligned.m8n8.x4.shared.b16 {%0,%1,%2,%3}, [%4];"
        : "=r"(r[0]), "=r"(r[1]), "=r"(r[2]), "=r"(r[3]) : "r"(a));
}
static __device__ __forceinline__ void ldm4t(uint32_t* r, uint32_t a){
    asm volatile("ldmatrix.sync.aligned.m8n8.x4.trans.shared.b16 {%0,%1,%2,%3}, [%4];"
        : "=r"(r[0]), "=r"(r[1]), "=r"(r[2]), "=r"(r[3]) : "r"(a));
}
static __device__ __forceinline__ void ldm2t(uint32_t* r, uint32_t a){
    asm volatile("ldmatrix.sync.aligned.m8n8.x2.trans.shared.b16 {%0,%1}, [%2];"
        : "=r"(r[0]), "=r"(r[1]) : "r"(a));
}
static __device__ __forceinline__ void mma16816(float* d, const uint32_t* a, uint32_t b0, uint32_t b1){
    asm volatile("mma.sync.aligned.m16n8k16.row.col.f32.f16.f16.f32 "
        "{%0,%1,%2,%3},{%4,%5,%6,%7},{%8,%9},{%0,%1,%2,%3};"
        : "+f"(d[0]), "+f"(d[1]), "+f"(d[2]), "+f"(d[3])
        : "r"(a[0]), "r"(a[1]), "r"(a[2]), "r"(a[3]), "r"(b0), "r"(b1));
}
static __device__ __forceinline__ void sts_v4(uint32_t a, uint32_t x, uint32_t y, uint32_t z, uint32_t w){
    asm volatile("st.shared.v4.b32 [%0], {%1,%2,%3,%4};" :: "r"(a), "r"(x), "r"(y), "r"(z), "r"(w) : "memory");
}
static __device__ __forceinline__ void lds_v4(uint32_t* r, uint32_t a){
    asm volatile("ld.shared.v4.b32 {%0,%1,%2,%3}, [%4];"
        : "=r"(r[0]), "=r"(r[1]), "=r"(r[2]), "=r"(r[3]) : "r"(a));
}
// K row addressing: 64B rows; 16B-chunk c rotated by (row>>1) so ldmatrix (8 rows, fixed c) is conflict-free
static __device__ __forceinline__ uint32_t kaddr(int n, int c){
    return (uint32_t)n*64u + ((((uint32_t)c + ((uint32_t)n >> 1)) & 3u) * 16u);
}

__global__ void __launch_bounds__(512, 1)
lepe_hmma(const float* __restrict__ qkv,
          const float* __restrict__ lw,
          const float* __restrict__ lb,
          float* __restrict__ out)
{
    extern __shared__ char sm[];
    const uint32_t smb = s2u(sm);
    const int tid = threadIdx.x;
    const int wid = tid >> 5, lane = tid & 31;

    const int bx = blockIdx.x;            // (window, head)
    const int win = bx >> 2, head = bx & 3;
    const int b  = win >> 6;
    const int tB = (win >> 4) & 3;
    const int wB = win & 15;
    const size_t batch_off = (size_t)b * Ll * Cc;
    const int chan  = head * HD;
    const int lbase = tB*8192 + wB*4;

    const float* qg = qkv + batch_off;
    const float* kg = qkv + (size_t)1*Bb*Ll*Cc + batch_off;
    const float* vg = qkv + (size_t)2*Bb*Ll*Cc + batch_off;

    // ---------- stage K fp16 (swizzled), V fp16 row-major (+ones pad) ----------
    {
        const int q = tid & 3;            // 4 threads per row, 8 d-values each
        const int rbase = tid >> 2;       // 0..127
        for (int it = 0; it < 4; it++){
            const int j = it*128 + rbase;
            const int t = j >> 8, h = (j >> 2) & 63, ws = j & 3;
            const size_t l = (size_t)(lbase + t*4096 + h*64 + ws);
            const float4 k0 = *(const float4*)(kg + l*Cc + chan + q*8);
            const float4 k1 = *(const float4*)(kg + l*Cc + chan + q*8 + 4);
            sts_v4(smb + KF_OFF + kaddr(j, q),
                   pk2h(k0.x, k0.y), pk2h(k0.z, k0.w),
                   pk2h(k1.x, k1.y), pk2h(k1.z, k1.w));

            const float4 v0 = *(const float4*)(vg + l*Cc + chan + q*8);
            const float4 v1 = *(const float4*)(vg + l*Cc + chan + q*8 + 4);
            sts_v4(smb + VH_OFF + (uint32_t)j*80u + (uint32_t)q*16u,
                   pk2h(v0.x, v0.y), pk2h(v0.z, v0.w),
                   pk2h(v1.x, v1.y), pk2h(v1.z, v1.w));
            if (q == 3)   // pad halves 32..39: d32 = 1.0 (tensor row-sum column), rest 0
                sts_v4(smb + VH_OFF + (uint32_t)j*80u + 64u, 0x00003C00u, 0u, 0u, 0u);
        }
        for (int idx = tid; idx < 27*32; idx += 512){
            const int tap = idx >> 5, d = idx & 31;
            ((float*)(sm + WS_OFF))[tap*32 + d] = lw[(chan + d)*27 + tap];
        }
        if (tid < 32) ((float*)(sm + BS_OFF))[tid] = lb[chan + tid];
    }

    // ---------- Q fragments from gmem (scaled into log2 domain, fp16) ----------
    const int qb = wid * 32;              // each warp owns 32 q-rows
    uint32_t qf[2][2][4];
    {
        const float sc = 0.17677669529663689f * 1.4426950408889634f;
        #pragma unroll
        for (int mt = 0; mt < 2; mt++){
            const int r0 = qb + mt*16 + (lane >> 2);
            const int r1 = r0 + 8;
            const int t0 = r0 >> 8, h0 = (r0 >> 2) & 63, w0 = r0 & 3;
            const int t1 = r1 >> 8, h1 = (r1 >> 2) & 63, w1 = r1 & 3;
            const float* p0 = qg + (size_t)(lbase + t0*4096 + h0*64 + w0)*Cc + chan;
            const float* p1 = qg + (size_t)(lbase + t1*4096 + h1*64 + w1)*Cc + chan;
            #pragma unroll
            for (int kt = 0; kt < 2; kt++){
                const int d0 = kt*16 + 2*(lane & 3);
                const float2 x0 = *(const float2*)(p0 + d0);
                const float2 x1 = *(const float2*)(p1 + d0);
                const float2 x2 = *(const float2*)(p0 + d0 + 8);
                const float2 x3 = *(const float2*)(p1 + d0 + 8);
                qf[mt][kt][0] = pk2h(x0.x*sc, x0.y*sc);
                qf[mt][kt][1] = pk2h(x1.x*sc, x1.y*sc);
                qf[mt][kt][2] = pk2h(x2.x*sc, x2.y*sc);
                qf[mt][kt][3] = pk2h(x3.x*sc, x3.y*sc);
            }
        }
    }
    __syncthreads();

    // ---------- mainloop: 32 subchunks of 16 keys ----------
    float oAcc[2][4][4];
    #pragma unroll
    for (int a = 0; a < 2; a++)
        #pragma unroll
        for (int b2 = 0; b2 < 4; b2++)
            #pragma unroll
            for (int c = 0; c < 4; c++) oAcc[a][b2][c] = 0.f;
    float oSum[2][4];
    #pragma unroll
    for (int a = 0; a < 2; a++)
        #pragma unroll
        for (int c = 0; c < 4; c++) oSum[a][c] = 0.f;

    const int lg = lane >> 3, lr = lane & 7;
    #pragma unroll 1
    for (int cs = 0; cs < 32; cs++){
        const int j0 = cs * 16;
        // V fragments via ldmatrix.trans from row-major fp16 V
        uint32_t vh[2][4];
        #pragma unroll
        for (int dg = 0; dg < 2; dg++){
            const uint32_t a = smb + VH_OFF
                + (uint32_t)(j0 + (lg & 1)*8 + lr)*80u
                + (uint32_t)dg*32u + (uint32_t)(lg >> 1)*16u;
            ldm4t(vh[dg], a);
        }
        // ones-column fragment (d=32..39): x2 trans, lanes 0-15 carry row addrs
        uint32_t vs2[2];
        ldm2t(vs2, smb + VH_OFF + (uint32_t)(j0 + (lane & 15))*80u + 64u);
        // K fragments (B operand for QK): tiles [8 keys x 8 d]
        uint32_t kh[2][4];
        #pragma unroll
        for (int nt = 0; nt < 2; nt++)
            ldm4(kh[nt], smb + KF_OFF + kaddr(j0 + nt*8 + lr, lg));
        // S = Q K^T (single fp16 term)
        float s[2][2][4];
        #pragma unroll
        for (int mt = 0; mt < 2; mt++)
            #pragma unroll
            for (int nt = 0; nt < 2; nt++){
                float* sd = s[mt][nt];
                sd[0]=sd[1]=sd[2]=sd[3]=0.f;
                mma16816(sd, qf[mt][0], kh[nt][0], kh[nt][1]);
                mma16816(sd, qf[mt][1], kh[nt][2], kh[nt][3]);
            }
        // softmax in f16x2 (pack then ex2.f16x2) + PV + tensor row-sum
        #pragma unroll
        for (int mt = 0; mt < 2; mt++){
            uint32_t ah[4];
            ah[0] = ex2h2(pk2h(s[mt][0][0], s[mt][0][1]));
            ah[1] = ex2h2(pk2h(s[mt][0][2], s[mt][0][3]));
            ah[2] = ex2h2(pk2h(s[mt][1][0], s[mt][1][1]));
            ah[3] = ex2h2(pk2h(s[mt][1][2], s[mt][1][3]));
            #pragma unroll
            for (int ntd = 0; ntd < 4; ntd++){
                const int dg = ntd >> 1;
                mma16816(oAcc[mt][ntd], ah, vh[dg][(ntd&1)*2], vh[dg][(ntd&1)*2+1]);
            }
            mma16816(oSum[mt], ah, vs2[0], vs2[1]);   // col d32 = Sum(p)
        }
    }

    // ---------- denominators from oSum (col 32 lives on lanes lane&3==0) ----------
    float ps[2][2];
    #pragma unroll
    for (int mt = 0; mt < 2; mt++){
        const float d0 = __shfl_sync(0xffffffffu, oSum[mt][0], lane & ~3);
        const float d1 = __shfl_sync(0xffffffffu, oSum[mt][2], lane & ~3);
        ps[mt][0] = 1.f / d0;
        ps[mt][1] = 1.f / d1;
    }
    #pragma unroll
    for (int mt = 0; mt < 2; mt++){
        const int r0 = qb + mt*16 + (lane >> 2);
        #pragma unroll
        for (int ntd = 0; ntd < 4; ntd++){
            const int cc = ntd*8 + 2*(lane & 3);
            float2 a, b2;
            a.x  = oAcc[mt][ntd][0] * ps[mt][0];
            a.y  = oAcc[mt][ntd][1] * ps[mt][0];
            b2.x = oAcc[mt][ntd][2] * ps[mt][1];
            b2.y = oAcc[mt][ntd][3] * ps[mt][1];
            *(float2*)(sm + OS_OFF + r0*144 + cc*4)      = a;
            *(float2*)(sm + OS_OFF + (r0+8)*144 + cc*4)  = b2;
        }
    }
    __syncthreads();

    // ---------- epilogue: t-paired LePE conv (fp16 V) + bias + store ----------
    {
        const int r    = tid & 255;
        const int half = tid >> 8;
        const int c0   = half * 16;
        const float* Wsm = (const float*)(sm + WS_OFF);
        const float* Bsm = (const float*)(sm + BS_OFF);

        float o0[16], o1[16];
        #pragma unroll
        for (int k = 0; k < 4; k++){
            const float4 f0 = *(const float4*)(sm + OS_OFF + r*144       + c0*4 + k*16);
            const float4 f1 = *(const float4*)(sm + OS_OFF + (r+256)*144 + c0*4 + k*16);
            o0[4*k+0]=f0.x; o0[4*k+1]=f0.y; o0[4*k+2]=f0.z; o0[4*k+3]=f0.w;
            o1[4*k+0]=f1.x; o1[4*k+1]=f1.y; o1[4*k+2]=f1.z; o1[4*k+3]=f1.w;
        }
        const int rh = (r >> 2) & 63, rws = r & 3;
        #pragma unroll
        for (int dh = -1; dh <= 1; dh++){
            const int hh = rh + dh;
            if ((unsigned)hh >= 64u) continue;
            #pragma unroll
            for (int dw = -1; dw <= 1; dw++){
                const int ww2 = rws + dw;
                if ((unsigned)ww2 >= 4u) continue;
                const int n2 = hh*4 + ww2;
                uint32_t v0p[8], v1p[8];
                const uint32_t a0 = smb + VH_OFF + (uint32_t)n2*80u + (uint32_t)c0*2u;
                lds_v4(v0p,     a0);
                lds_v4(v0p + 4, a0 + 16u);
                lds_v4(v1p,     a0 + 256u*80u);
                lds_v4(v1p + 4, a0 + 256u*80u + 16u);
                const int wb = (dh+1)*3 + (dw+1);
                const float* w0 = Wsm + (     wb)*32 + c0;   // dt=-1 tap
                const float* w1 = Wsm + ( 9 + wb)*32 + c0;   // dt= 0 tap
                const float* w2 = Wsm + (18 + wb)*32 + c0;   // dt=+1 tap
                #pragma unroll
                for (int i = 0; i < 8; i++){
                    const float2 x0 = __half22float2(*reinterpret_cast<const __half2*>(&v0p[i]));
                    const float2 x1 = __half22float2(*reinterpret_cast<const __half2*>(&v1p[i]));
                    o0[2*i]   += w1[2*i]*x0.x   + w2[2*i]*x1.x;
                    o0[2*i+1] += w1[2*i+1]*x0.y + w2[2*i+1]*x1.y;
                    o1[2*i]   += w0[2*i]*x0.x   + w1[2*i]*x1.x;
                    o1[2*i+1] += w0[2*i+1]*x0.y + w1[2*i+1]*x1.y;
                }
            }
        }
        const size_t l0 = (size_t)(lbase +        rh*64 + rws);
        const size_t l1 = (size_t)(lbase + 4096 + rh*64 + rws);
        float* op0 = out + batch_off + l0*Cc + chan + c0;
        float* op1 = out + batch_off + l1*Cc + chan + c0;
        #pragma unroll
        for (int k = 0; k < 4; k++){
            float4 r4;
            r4.x = o0[4*k+0] + Bsm[c0+4*k+0];
            r4.y = o0[4*k+1] + Bsm[c0+4*k+1];
            r4.z = o0[4*k+2] + Bsm[c0+4*k+2];
            r4.w = o0[4*k+3] + Bsm[c0+4*k+3];
            ((float4*)op0)[k] = r4;
            r4.x = o1[4*k+0] + Bsm[c0+4*k+0];
            r4.y = o1[4*k+1] + Bsm[c0+4*k+1];
            r4.z = o1[4*k+2] + Bsm[c0+4*k+2];
            r4.w = o1[4*k+3] + Bsm[c0+4*k+3];
            ((float4*)op1)[k] = r4;
        }
    }
}

extern "C" void kernel_launch(void* const* d_in, const int* in_sizes, int n_in,
                              void* d_out, int out_size)
{
    const float* qkv = (const float*)d_in[0];
    const float* lw  = (const float*)d_in[1];
    const float* lb  = (const float*)d_in[2];
    float* out       = (float*)d_out;

    cudaFuncSetAttribute(lepe_hmma, cudaFuncAttributeMaxDynamicSharedMemorySize, SMEM_BYTES);
    lepe_hmma<<<512, 512, SMEM_BYTES>>>(qkv, lw, lb, out);
}

// round 11
// speedup vs baseline: 2.1140x; 1.0254x over previous
#include <cuda_runtime.h>
#include <cuda_fp16.h>
#include <cstdint>

#define Bb 2
#define Ll 32768
#define Cc 128
#define NTOK 512
#define HD 32

// ---- smem byte offsets (per 256-thread CTA) ----
#define KF_OFF  0           // K fp16: 512 rows x 64B (swizzled)      32768
#define VH_OFF  32768       // V fp16 row-major: 512 rows x 80B       40960
                            //   (halves 32..39 = pad: d32=1.0 -> tensor row-sums)
#define OS_OFF  73728       // O fp32 [256][36] staging               36864
#define WS_OFF  110592      // weights [27][32] f32                    3456
#define BS_OFF  114048      // bias [32] f32                            128
#define SMEM_BYTES 114176   // x2 CTAs = 228352 <= 228KB/SM

static __device__ __forceinline__ uint32_t s2u(const void* p){
    uint32_t a;
    asm("{ .reg .u64 t; cvta.to.shared.u64 t, %1; cvt.u32.u64 %0, t; }" : "=r"(a) : "l"(p));
    return a;
}
static __device__ __forceinline__ uint32_t pk2h(float a, float b){
    uint32_t r; asm("cvt.rn.f16x2.f32 %0, %1, %2;" : "=r"(r) : "f"(b), "f"(a)); return r;
}
static __device__ __forceinline__ uint32_t ex2h2(uint32_t a){
    uint32_t r; asm("ex2.approx.f16x2 %0, %1;" : "=r"(r) : "r"(a)); return r;
}
static __device__ __forceinline__ void ldm4(uint32_t* r, uint32_t a){
    asm volatile("ldmatrix.sync.aligned.m8n8.x4.shared.b16 {%0,%1,%2,%3}, [%4];"
        : "=r"(r[0]), "=r"(r[1]), "=r"(r[2]), "=r"(r[3]) : "r"(a));
}
static __device__ __forceinline__ void ldm4t(uint32_t* r, uint32_t a){
    asm volatile("ldmatrix.sync.aligned.m8n8.x4.trans.shared.b16 {%0,%1,%2,%3}, [%4];"
        : "=r"(r[0]), "=r"(r[1]), "=r"(r[2]), "=r"(r[3]) : "r"(a));
}
static __device__ __forceinline__ void ldm2t(uint32_t* r, uint32_t a){
    asm volatile("ldmatrix.sync.aligned.m8n8.x2.trans.shared.b16 {%0,%1}, [%2];"
        : "=r"(r[0]), "=r"(r[1]) : "r"(a));
}
static __device__ __forceinline__ void mma16816(float* d, const uint32_t* a, uint32_t b0, uint32_t b1){
    asm volatile("mma.sync.aligned.m16n8k16.row.col.f32.f16.f16.f32 "
        "{%0,%1,%2,%3},{%4,%5,%6,%7},{%8,%9},{%0,%1,%2,%3};"
        : "+f"(d[0]), "+f"(d[1]), "+f"(d[2]), "+f"(d[3])
        : "r"(a[0]), "r"(a[1]), "r"(a[2]), "r"(a[3]), "r"(b0), "r"(b1));
}
static __device__ __forceinline__ void sts_v4(uint32_t a, uint32_t x, uint32_t y, uint32_t z, uint32_t w){
    asm volatile("st.shared.v4.b32 [%0], {%1,%2,%3,%4};" :: "r"(a), "r"(x), "r"(y), "r"(z), "r"(w) : "memory");
}
static __device__ __forceinline__ void lds_v4(uint32_t* r, uint32_t a){
    asm volatile("ld.shared.v4.b32 {%0,%1,%2,%3}, [%4];"
        : "=r"(r[0]), "=r"(r[1]), "=r"(r[2]), "=r"(r[3]) : "r"(a));
}
// K row addressing: 64B rows; 16B-chunk c rotated by (row>>1) -> conflict-free ldmatrix
static __device__ __forceinline__ uint32_t kaddr(int n, int c){
    return (uint32_t)n*64u + ((((uint32_t)c + ((uint32_t)n >> 1)) & 3u) * 16u);
}

__global__ void __launch_bounds__(256, 2)
lepe_hmma(const float* __restrict__ qkv,
          const float* __restrict__ lw,
          const float* __restrict__ lb,
          float* __restrict__ out)
{
    extern __shared__ char sm[];
    const uint32_t smb = s2u(sm);
    const int tid = threadIdx.x;
    const int wid = tid >> 5, lane = tid & 31;

    const int bx = blockIdx.x;            // (window, head, qhalf)
    const int win = bx >> 3, head = (bx >> 1) & 3, qhalf = bx & 1;
    const int b  = win >> 6;
    const int tB = (win >> 4) & 3;
    const int wB = win & 15;
    const size_t batch_off = (size_t)b * Ll * Cc;
    const int chan  = head * HD;
    const int lbase = tB*8192 + wB*4;

    const float* qg = qkv + batch_off;
    const float* kg = qkv + (size_t)1*Bb*Ll*Cc + batch_off;
    const float* vg = qkv + (size_t)2*Bb*Ll*Cc + batch_off;

    // ---------- stage K fp16 (swizzled), V fp16 row-major (+ones pad) ----------
    {
        const int q = tid & 3;            // 4 threads per row, 8 d-values each
        const int rbase = tid >> 2;       // 0..63
        for (int it = 0; it < 8; it++){
            const int j = it*64 + rbase;
            const int t = j >> 8, h = (j >> 2) & 63, ws = j & 3;
            const size_t l = (size_t)(lbase + t*4096 + h*64 + ws);
            const float4 k0 = *(const float4*)(kg + l*Cc + chan + q*8);
            const float4 k1 = *(const float4*)(kg + l*Cc + chan + q*8 + 4);
            sts_v4(smb + KF_OFF + kaddr(j, q),
                   pk2h(k0.x, k0.y), pk2h(k0.z, k0.w),
                   pk2h(k1.x, k1.y), pk2h(k1.z, k1.w));

            const float4 v0 = *(const float4*)(vg + l*Cc + chan + q*8);
            const float4 v1 = *(const float4*)(vg + l*Cc + chan + q*8 + 4);
            sts_v4(smb + VH_OFF + (uint32_t)j*80u + (uint32_t)q*16u,
                   pk2h(v0.x, v0.y), pk2h(v0.z, v0.w),
                   pk2h(v1.x, v1.y), pk2h(v1.z, v1.w));
            if (q == 3)   // pad: d32 = 1.0 (tensor row-sum column), rest 0
                sts_v4(smb + VH_OFF + (uint32_t)j*80u + 64u, 0x00003C00u, 0u, 0u, 0u);
        }
        for (int idx = tid; idx < 27*32; idx += 256){
            const int tap = idx >> 5, d = idx & 31;
            ((float*)(sm + WS_OFF))[tap*32 + d] = lw[(chan + d)*27 + tap];
        }
        if (tid < 32) ((float*)(sm + BS_OFF))[tid] = lb[chan + tid];
    }

    // ---------- Q fragments from gmem (scaled into log2 domain, fp16) ----------
    const int qb  = qhalf*256 + wid*32;   // global q-row base for this warp
    const int qbl = wid*32;               // local (within-CTA) row base
    uint32_t qf[2][2][4];
    {
        const float sc = 0.17677669529663689f * 1.4426950408889634f;
        #pragma unroll
        for (int mt = 0; mt < 2; mt++){
            const int r0 = qb + mt*16 + (lane >> 2);
            const int r1 = r0 + 8;
            const int t0 = r0 >> 8, h0 = (r0 >> 2) & 63, w0 = r0 & 3;
            const int t1 = r1 >> 8, h1 = (r1 >> 2) & 63, w1 = r1 & 3;
            const float* p0 = qg + (size_t)(lbase + t0*4096 + h0*64 + w0)*Cc + chan;
            const float* p1 = qg + (size_t)(lbase + t1*4096 + h1*64 + w1)*Cc + chan;
            #pragma unroll
            for (int kt = 0; kt < 2; kt++){
                const int d0 = kt*16 + 2*(lane & 3);
                const float2 x0 = *(const float2*)(p0 + d0);
                const float2 x1 = *(const float2*)(p1 + d0);
                const float2 x2 = *(const float2*)(p0 + d0 + 8);
                const float2 x3 = *(const float2*)(p1 + d0 + 8);
                qf[mt][kt][0] = pk2h(x0.x*sc, x0.y*sc);
                qf[mt][kt][1] = pk2h(x1.x*sc, x1.y*sc);
                qf[mt][kt][2] = pk2h(x2.x*sc, x2.y*sc);
                qf[mt][kt][3] = pk2h(x3.x*sc, x3.y*sc);
            }
        }
    }
    __syncthreads();

    // ---------- mainloop: 32 subchunks of 16 keys ----------
    float oAcc[2][4][4];
    #pragma unroll
    for (int a = 0; a < 2; a++)
        #pragma unroll
        for (int b2 = 0; b2 < 4; b2++)
            #pragma unroll
            for (int c = 0; c < 4; c++) oAcc[a][b2][c] = 0.f;
    float oSum[2][4];
    #pragma unroll
    for (int a = 0; a < 2; a++)
        #pragma unroll
        for (int c = 0; c < 4; c++) oSum[a][c] = 0.f;

    const int lg = lane >> 3, lr = lane & 7;
    // ones-column fragment is row-independent -> hoist out of the loop
    uint32_t vs2[2];
    ldm2t(vs2, smb + VH_OFF + (uint32_t)(lane & 15)*80u + 64u);

    #pragma unroll 1
    for (int cs = 0; cs < 32; cs++){
        const int j0 = cs * 16;
        // K fragments (B operand for QK)
        uint32_t kh[2][4];
        #pragma unroll
        for (int nt = 0; nt < 2; nt++)
            ldm4(kh[nt], smb + KF_OFF + kaddr(j0 + nt*8 + lr, lg));
        // V fragments via ldmatrix.trans from row-major fp16 V
        uint32_t vh[2][4];
        #pragma unroll
        for (int dg = 0; dg < 2; dg++){
            const uint32_t a = smb + VH_OFF
                + (uint32_t)(j0 + (lg & 1)*8 + lr)*80u
                + (uint32_t)dg*32u + (uint32_t)(lg >> 1)*16u;
            ldm4t(vh[dg], a);
        }
        // S = Q K^T (single fp16 term)
        float s[2][2][4];
        #pragma unroll
        for (int mt = 0; mt < 2; mt++)
            #pragma unroll
            for (int nt = 0; nt < 2; nt++){
                float* sd = s[mt][nt];
                sd[0]=sd[1]=sd[2]=sd[3]=0.f;
                mma16816(sd, qf[mt][0], kh[nt][0], kh[nt][1]);
                mma16816(sd, qf[mt][1], kh[nt][2], kh[nt][3]);
            }
        // softmax in f16x2 + PV + tensor row-sum
        #pragma unroll
        for (int mt = 0; mt < 2; mt++){
            uint32_t ah[4];
            ah[0] = ex2h2(pk2h(s[mt][0][0], s[mt][0][1]));
            ah[1] = ex2h2(pk2h(s[mt][0][2], s[mt][0][3]));
            ah[2] = ex2h2(pk2h(s[mt][1][0], s[mt][1][1]));
            ah[3] = ex2h2(pk2h(s[mt][1][2], s[mt][1][3]));
            #pragma unroll
            for (int ntd = 0; ntd < 4; ntd++){
                const int dg = ntd >> 1;
                mma16816(oAcc[mt][ntd], ah, vh[dg][(ntd&1)*2], vh[dg][(ntd&1)*2+1]);
            }
            mma16816(oSum[mt], ah, vs2[0], vs2[1]);   // col d32 = Sum(p)
        }
    }

    // ---------- denominators (col 32 lives on lanes lane&3==0), stage O ----------
    float ps[2][2];
    #pragma unroll
    for (int mt = 0; mt < 2; mt++){
        const float d0 = __shfl_sync(0xffffffffu, oSum[mt][0], lane & ~3);
        const float d1 = __shfl_sync(0xffffffffu, oSum[mt][2], lane & ~3);
        ps[mt][0] = 1.f / d0;
        ps[mt][1] = 1.f / d1;
    }
    #pragma unroll
    for (int mt = 0; mt < 2; mt++){
        const int r0 = qbl + mt*16 + (lane >> 2);   // local row
        #pragma unroll
        for (int ntd = 0; ntd < 4; ntd++){
            const int cc = ntd*8 + 2*(lane & 3);
            float2 a, b2;
            a.x  = oAcc[mt][ntd][0] * ps[mt][0];
            a.y  = oAcc[mt][ntd][1] * ps[mt][0];
            b2.x = oAcc[mt][ntd][2] * ps[mt][1];
            b2.y = oAcc[mt][ntd][3] * ps[mt][1];
            *(float2*)(sm + OS_OFF + r0*144 + cc*4)      = a;
            *(float2*)(sm + OS_OFF + (r0+8)*144 + cc*4)  = b2;
        }
    }
    __syncthreads();

    // ---------- epilogue: LePE conv (fp16 V) + bias + store (one row/thread) ----------
    {
        const int r = tid;                 // local row 0..255 ; global row = qhalf*256 + r
        const float* Wsm = (const float*)(sm + WS_OFF);
        const float* Bsm = (const float*)(sm + BS_OFF);

        float o[32];
        #pragma unroll
        for (int k = 0; k < 8; k++){
            const float4 f = *(const float4*)(sm + OS_OFF + r*144 + k*16);
            o[4*k+0]=f.x; o[4*k+1]=f.y; o[4*k+2]=f.z; o[4*k+3]=f.w;
        }
        const int rh = (r >> 2) & 63, rws = r & 3;
        #pragma unroll
        for (int dt = -1; dt <= 1; dt++){
            const int tt = qhalf + dt;
            if ((unsigned)tt >= 2u) continue;
            #pragma unroll
            for (int dh = -1; dh <= 1; dh++){
                const int hh = rh + dh;
                if ((unsigned)hh >= 64u) continue;
                #pragma unroll
                for (int dw = -1; dw <= 1; dw++){
                    const int ww2 = rws + dw;
                    if ((unsigned)ww2 >= 4u) continue;
                    const int n2 = tt*256 + hh*4 + ww2;
                    uint32_t vp[8];
                    const uint32_t a0 = smb + VH_OFF + (uint32_t)n2*80u;
                    lds_v4(vp,     a0);
                    lds_v4(vp + 4, a0 + 16u);
                    const float* wr = Wsm + ((dt+1)*9 + (dh+1)*3 + (dw+1))*32;
                    #pragma unroll
                    for (int i = 0; i < 16; i++){
                        const float2 x = __half22float2(*reinterpret_cast<const __half2*>(&vp[i & 7]));
                        // unrolled as 8 half2 words = 16 channels-pairs
                        (void)x;
                    }
                    #pragma unroll
                    for (int i = 0; i < 8; i++){
                        const float2 x = __half22float2(*reinterpret_cast<const __half2*>(&vp[i]));
                        o[2*i]   += wr[2*i]   * x.x;
                        o[2*i+1] += wr[2*i+1] * x.y;
                    }
                    #pragma unroll
                    for (int i = 0; i < 8; i++){
                        // channels 16..31 live in the same 8 words? no: vp covers 32B=16 ch; need next 32B
                    }
                    uint32_t vq[8];
                    lds_v4(vq,     a0 + 32u);
                    lds_v4(vq + 4, a0 + 48u);
                    #pragma unroll
                    for (int i = 0; i < 8; i++){
                        const float2 x = __half22float2(*reinterpret_cast<const __half2*>(&vq[i]));
                        o[16+2*i]   += wr[16+2*i]   * x.x;
                        o[16+2*i+1] += wr[16+2*i+1] * x.y;
                    }
                }
            }
        }
        const size_t l = (size_t)(lbase + qhalf*4096 + rh*64 + rws);
        float* op = out + batch_off + l*Cc + chan;
        #pragma unroll
        for (int k = 0; k < 8; k++){
            float4 r4;
            r4.x = o[4*k+0] + Bsm[4*k+0];
            r4.y = o[4*k+1] + Bsm[4*k+1];
            r4.z = o[4*k+2] + Bsm[4*k+2];
            r4.w = o[4*k+3] + Bsm[4*k+3];
            ((float4*)op)[k] = r4;
        }
    }
}

extern "C" void kernel_launch(void* const* d_in, const int* in_sizes, int n_in,
                              void* d_out, int out_size)
{
    const float* qkv = (const float*)d_in[0];
    const float* lw  = (const float*)d_in[1];
    const float* lb  = (const float*)d_in[2];
    float* out       = (float*)d_out;

    cudaFuncSetAttribute(lepe_hmma, cudaFuncAttributeMaxDynamicSharedMemorySize, SMEM_BYTES);
    lepe_hmma<<<1024, 256, SMEM_BYTES>>>(qkv, lw, lb, out);
}